// round 10
// baseline (speedup 1.0000x reference)
#include <cuda_runtime.h>

// FoldLayer fold (col2im), K=3, S=2, D=1, pad=1, cropped.
// patches: (B=16, GH=64, GW=64, 9*128) fp32, slot-major (i*3+j)*128+c
// out:     (B=16, 128, 128, 128) fp32
//
// Quad-gather (one warp per 2x2 output quad), same dataflow as R5 winner:
//   out(2Y,  2X)   = P(Y,X)[s4]
//   out(2Y,  2X+1) = P(Y,X)[s5] + P(Y,X+1)[s3]
//   out(2Y+1,2X)   = P(Y,X)[s7] + P(Y+1,X)[s1]
//   out(2Y+1,2X+1) = P(Y,X)[s8] + P(Y,X+1)[s6] + P(Y+1,X)[s2] + P(Y+1,X+1)[s0]
//
// R8 change: warp->quad mapping swizzled so quad-rows (2Y, 2Y+1) are adjacent
// in scheduling order (each 8-warp block = 2 quad-rows x 4 X). A patch row's
// full 4608B is then consumed by temporally-adjacent warps (slots 0-2 by the
// row above, slots 3-8 by its own row), turning the previous 2/3-1/3 split
// sweep into contiguous DRAM bursts. All accesses use streaming (.cs) hints:
// zero reuse anywhere, keep L2 free for write drain.

#define GH_  64
#define GW_  64
#define C4_  32              // 128 floats = 32 float4 per lane-vector
#define PSTRIDE (9 * C4_)    // float4s per patch = 288

__device__ __forceinline__ void acc4(float4& a, const float4 v) {
    a.x += v.x; a.y += v.y; a.z += v.z; a.w += v.w;
}

__global__ __launch_bounds__(256)
void fold_quad_kernel(const float4* __restrict__ p, float4* __restrict__ out) {
    const int warp = (blockIdx.x * blockDim.x + threadIdx.x) >> 5;
    const int lane = threadIdx.x & 31;

    // 65536 warps, one per quad. Swizzled order: (b, Y>>1, X, Y&1) —
    // consecutive warp pairs cover quad-rows Y, Y+1 at the same X.
    const int yl = warp & 1;
    const int X  = (warp >> 1) & 63;
    const int Yp = (warp >> 7) & 31;
    const int b  = warp >> 12;
    const int Y  = (Yp << 1) | yl;

    const bool okX = (X < 63);
    const bool okY = (Y < 63);

    // float4 base of patch (Y,X), this lane's channel chunk
    const int pb  = ((b * GH_ + Y) * GW_ + X) * PSTRIDE + lane;
    const int p01 = pb + PSTRIDE;              // patch (Y, X+1)
    const int p10 = pb + GW_ * PSTRIDE;        // patch (Y+1, X)
    const int p11 = p10 + PSTRIDE;             // patch (Y+1, X+1)

    const float4 z = make_float4(0.f, 0.f, 0.f, 0.f);

    // All 9 loads issued up front (streaming, evict-first), guarded ones predicated.
    const float4 v4 = __ldcs(&p[pb  + 4 * C4_]);
    const float4 v5 = __ldcs(&p[pb  + 5 * C4_]);
    const float4 v7 = __ldcs(&p[pb  + 7 * C4_]);
    const float4 v8 = __ldcs(&p[pb  + 8 * C4_]);
    const float4 v3 = okX ? __ldcs(&p[p01 + 3 * C4_]) : z;
    const float4 v6 = okX ? __ldcs(&p[p01 + 6 * C4_]) : z;
    const float4 v1 = okY ? __ldcs(&p[p10 + 1 * C4_]) : z;
    const float4 v2 = okY ? __ldcs(&p[p10 + 2 * C4_]) : z;
    const float4 v0 = (okX && okY) ? __ldcs(&p[p11]) : z;

    float4 a00 = v4;
    float4 a01 = v5;  acc4(a01, v3);
    float4 a10 = v7;  acc4(a10, v1);
    float4 a11 = v8;  acc4(a11, v6);  acc4(a11, v2);  acc4(a11, v0);

    // output base: pixel (2Y, 2X); streaming stores (never re-read)
    const int ob = ((b * 128 + 2 * Y) * 128 + 2 * X) * C4_ + lane;
    __stcs(&out[ob],             a00);
    __stcs(&out[ob + C4_],       a01);
    __stcs(&out[ob + 128 * C4_], a10);
    __stcs(&out[ob + 129 * C4_], a11);
}

extern "C" void kernel_launch(void* const* d_in, const int* in_sizes, int n_in,
                              void* d_out, int out_size) {
    (void)in_sizes; (void)n_in; (void)out_size;
    const float4* p = (const float4*)d_in[0];
    float4* out = (float4*)d_out;

    // 65536 warps total, 8 warps (256 threads) per block -> 8192 blocks
    fold_quad_kernel<<<8192, 256>>>(p, out);
}

// round 13
// speedup vs baseline: 1.0044x; 1.0044x over previous
#include <cuda_runtime.h>

// FoldLayer fold (col2im), K=3, S=2, D=1, pad=1, cropped.
// patches: (B=16, GH=64, GW=64, 9*128) fp32, slot-major (i*3+j)*128+c
// out:     (B=16, 128, 128, 128) fp32
//
// Pair-quad gather: one warp per 2x4 output tile (two adjacent-X 2x2 quads).
// Quad at (Y,X):
//   out(2Y,  2X)   = P(Y,X)[s4]
//   out(2Y,  2X+1) = P(Y,X)[s5] + P(Y,X+1)[s3]
//   out(2Y+1,2X)   = P(Y,X)[s7] + P(Y+1,X)[s1]
//   out(2Y+1,2X+1) = P(Y,X)[s8] + P(Y,X+1)[s6] + P(Y+1,X)[s2] + P(Y+1,X+1)[s0]
// Processing quads X0=2*Xp and X0+1 together gives 18 independent LDG.128s
// per warp (deep MLP) and 2KB-contiguous store runs per output row.
// (Re-submission of R10 candidate: previous run died to a container
// infrastructure failure before producing any kernel-level signal.)

#define GH_  64
#define GW_  64
#define C4_  32              // 128 floats = 32 float4 per lane
#define PSTRIDE (9 * C4_)    // float4s per patch = 288
#define ROWSTRIDE (GW_ * PSTRIDE)

__device__ __forceinline__ void acc4(float4& a, const float4 v) {
    a.x += v.x; a.y += v.y; a.z += v.z; a.w += v.w;
}

__global__ __launch_bounds__(256)
void fold_pair_kernel(const float4* __restrict__ p, float4* __restrict__ out) {
    const int warp = (blockIdx.x * blockDim.x + threadIdx.x) >> 5;
    const int lane = threadIdx.x & 31;

    // 32768 warps: (b, Y, Xp) with Xp = X/2
    const int Xp = warp & 31;
    const int Y  = (warp >> 5) & 63;
    const int b  = warp >> 11;
    const int X0 = Xp << 1;            // 0..62, even

    const bool okY  = (Y < 63);
    const bool okX1 = (X0 < 62);       // X0+2 <= 63 ; false only at Xp=31

    const int pbA = ((b * GH_ + Y) * GW_ + X0) * PSTRIDE + lane;  // patch (Y,X0)
    const int pbB = pbA + PSTRIDE;                                // patch (Y,X0+1)
    const int pcA = pbA + ROWSTRIDE;                              // patch (Y+1,X0)
    const int pcB = pcA + PSTRIDE;                                // patch (Y+1,X0+1)

    const float4 z = make_float4(0.f, 0.f, 0.f, 0.f);

    // ---- 18 loads issued up front (independent -> deep MLP) ----
    // Quad A (X0): right-neighbor patch is (Y,X0+1), always in range.
    const float4 A4 = __ldg(&p[pbA + 4 * C4_]);
    const float4 A5 = __ldg(&p[pbA + 5 * C4_]);
    const float4 A7 = __ldg(&p[pbA + 7 * C4_]);
    const float4 A8 = __ldg(&p[pbA + 8 * C4_]);
    const float4 A3 = __ldg(&p[pbB + 3 * C4_]);
    const float4 A6 = __ldg(&p[pbB + 6 * C4_]);
    const float4 A1 = okY ? __ldg(&p[pcA + 1 * C4_]) : z;
    const float4 A2 = okY ? __ldg(&p[pcA + 2 * C4_]) : z;
    const float4 A0 = okY ? __ldg(&p[pcB + 0 * C4_]) : z;

    // Quad B (X0+1): right-neighbor patch is (Y,X0+2), guarded by okX1.
    const float4 B4 = __ldg(&p[pbB + 4 * C4_]);
    const float4 B5 = __ldg(&p[pbB + 5 * C4_]);
    const float4 B7 = __ldg(&p[pbB + 7 * C4_]);
    const float4 B8 = __ldg(&p[pbB + 8 * C4_]);
    const float4 B3 = okX1 ? __ldg(&p[pbB + PSTRIDE + 3 * C4_]) : z;
    const float4 B6 = okX1 ? __ldg(&p[pbB + PSTRIDE + 6 * C4_]) : z;
    const float4 B1 = okY ? __ldg(&p[pcB + 1 * C4_]) : z;
    const float4 B2 = okY ? __ldg(&p[pcB + 2 * C4_]) : z;
    const float4 B0 = (okY && okX1) ? __ldg(&p[pcB + PSTRIDE + 0 * C4_]) : z;

    // ---- accumulate ----
    float4 a00 = A4;
    float4 a01 = A5;  acc4(a01, A3);
    float4 a10 = A7;  acc4(a10, A1);
    float4 a11 = A8;  acc4(a11, A6);  acc4(a11, A2);  acc4(a11, A0);

    float4 b00 = B4;
    float4 b01 = B5;  acc4(b01, B3);
    float4 b10 = B7;  acc4(b10, B1);
    float4 b11 = B8;  acc4(b11, B6);  acc4(b11, B2);  acc4(b11, B0);

    // ---- stores: two 2KB-contiguous runs (4 pixels per output row) ----
    const int ob = ((b * 128 + 2 * Y) * 128 + 2 * X0) * C4_ + lane;  // (2Y, 2X0)
    out[ob]                      = a00;
    out[ob + 1 * C4_]            = a01;
    out[ob + 2 * C4_]            = b00;
    out[ob + 3 * C4_]            = b01;
    const int ob2 = ob + 128 * C4_;                                  // (2Y+1, 2X0)
    out[ob2]                     = a10;
    out[ob2 + 1 * C4_]           = a11;
    out[ob2 + 2 * C4_]           = b10;
    out[ob2 + 3 * C4_]           = b11;
}

extern "C" void kernel_launch(void* const* d_in, const int* in_sizes, int n_in,
                              void* d_out, int out_size) {
    (void)in_sizes; (void)n_in; (void)out_size;
    const float4* p = (const float4*)d_in[0];
    float4* out = (float4*)d_out;

    // 32768 warps total, 8 warps (256 threads) per block -> 4096 blocks
    fold_pair_kernel<<<4096, 256>>>(p, out);
}

// round 15
// speedup vs baseline: 1.0112x; 1.0068x over previous
#include <cuda_runtime.h>

// FoldLayer fold (col2im), K=3, S=2, D=1, pad=1, cropped.
// patches: (B=16, GH=64, GW=64, 9*128) fp32, slot-major (i*3+j)*128+c
// out:     (B=16, 128, 128, 128) fp32
//
// Pair-quad gather: one warp per 2x4 output tile (two adjacent-X 2x2 quads).
// Quad at (Y,X):
//   out(2Y,  2X)   = P(Y,X)[s4]
//   out(2Y,  2X+1) = P(Y,X)[s5] + P(Y,X+1)[s3]
//   out(2Y+1,2X)   = P(Y,X)[s7] + P(Y+1,X)[s1]
//   out(2Y+1,2X+1) = P(Y,X)[s8] + P(Y,X+1)[s6] + P(Y+1,X)[s2] + P(Y+1,X+1)[s0]
//
// L=18 loads/warp @ ~78 regs is the modeled in-flight-bytes optimum
// (3 blocks/SM x 24 warps x 18 = 432 outstanding LDG.128 per SM; both
// shallower L=9 and deeper L=36 tilings yield fewer). launch_bounds(256,3)
// pins the 3-block residency. Unconditional loads hoisted ahead of the
// predicated edge loads to front-batch the common-path MLP.

#define GH_  64
#define GW_  64
#define C4_  32              // 128 floats = 32 float4 per lane
#define PSTRIDE (9 * C4_)    // float4s per patch = 288
#define ROWSTRIDE (GW_ * PSTRIDE)

__device__ __forceinline__ void acc4(float4& a, const float4 v) {
    a.x += v.x; a.y += v.y; a.z += v.z; a.w += v.w;
}

__global__ __launch_bounds__(256, 3)
void fold_pair_kernel(const float4* __restrict__ p, float4* __restrict__ out) {
    const int warp = (blockIdx.x * blockDim.x + threadIdx.x) >> 5;
    const int lane = threadIdx.x & 31;

    // 32768 warps: (b, Y, Xp) with Xp = X/2
    const int Xp = warp & 31;
    const int Y  = (warp >> 5) & 63;
    const int b  = warp >> 11;
    const int X0 = Xp << 1;            // 0..62, even

    const bool okY  = (Y < 63);
    const bool okX1 = (X0 < 62);       // X0+2 <= 63 ; false only at Xp=31

    const int pbA = ((b * GH_ + Y) * GW_ + X0) * PSTRIDE + lane;  // patch (Y,X0)
    const int pbB = pbA + PSTRIDE;                                // patch (Y,X0+1)
    const int pcA = pbA + ROWSTRIDE;                              // patch (Y+1,X0)
    const int pcB = pcA + PSTRIDE;                                // patch (Y+1,X0+1)

    const float4 z = make_float4(0.f, 0.f, 0.f, 0.f);

    // ---- 10 unconditional loads first: clean front batch, no predicate
    //      setup interleaved with the issue stream ----
    const float4 A4 = __ldg(&p[pbA + 4 * C4_]);
    const float4 A5 = __ldg(&p[pbA + 5 * C4_]);
    const float4 A7 = __ldg(&p[pbA + 7 * C4_]);
    const float4 A8 = __ldg(&p[pbA + 8 * C4_]);
    const float4 A3 = __ldg(&p[pbB + 3 * C4_]);
    const float4 A6 = __ldg(&p[pbB + 6 * C4_]);
    const float4 B4 = __ldg(&p[pbB + 4 * C4_]);
    const float4 B5 = __ldg(&p[pbB + 5 * C4_]);
    const float4 B7 = __ldg(&p[pbB + 7 * C4_]);
    const float4 B8 = __ldg(&p[pbB + 8 * C4_]);

    // ---- 8 predicated edge loads (warp-uniform predicates) ----
    const float4 A1 = okY ? __ldg(&p[pcA + 1 * C4_]) : z;
    const float4 A2 = okY ? __ldg(&p[pcA + 2 * C4_]) : z;
    const float4 A0 = okY ? __ldg(&p[pcB + 0 * C4_]) : z;
    const float4 B1 = okY ? __ldg(&p[pcB + 1 * C4_]) : z;
    const float4 B2 = okY ? __ldg(&p[pcB + 2 * C4_]) : z;
    const float4 B3 = okX1 ? __ldg(&p[pbB + PSTRIDE + 3 * C4_]) : z;
    const float4 B6 = okX1 ? __ldg(&p[pbB + PSTRIDE + 6 * C4_]) : z;
    const float4 B0 = (okY && okX1) ? __ldg(&p[pcB + PSTRIDE + 0 * C4_]) : z;

    // ---- accumulate ----
    float4 a00 = A4;
    float4 a01 = A5;  acc4(a01, A3);
    float4 a10 = A7;  acc4(a10, A1);
    float4 a11 = A8;  acc4(a11, A6);  acc4(a11, A2);  acc4(a11, A0);

    float4 b00 = B4;
    float4 b01 = B5;  acc4(b01, B3);
    float4 b10 = B7;  acc4(b10, B1);
    float4 b11 = B8;  acc4(b11, B6);  acc4(b11, B2);  acc4(b11, B0);

    // ---- stores: two 2KB-contiguous runs (4 pixels per output row) ----
    const int ob = ((b * 128 + 2 * Y) * 128 + 2 * X0) * C4_ + lane;  // (2Y, 2X0)
    out[ob]            = a00;
    out[ob + 1 * C4_]  = a01;
    out[ob + 2 * C4_]  = b00;
    out[ob + 3 * C4_]  = b01;
    const int ob2 = ob + 128 * C4_;                                  // (2Y+1, 2X0)
    out[ob2]           = a10;
    out[ob2 + 1 * C4_] = a11;
    out[ob2 + 2 * C4_] = b10;
    out[ob2 + 3 * C4_] = b11;
}

extern "C" void kernel_launch(void* const* d_in, const int* in_sizes, int n_in,
                              void* d_out, int out_size) {
    (void)in_sizes; (void)n_in; (void)out_size;
    const float4* p = (const float4*)d_in[0];
    float4* out = (float4*)d_out;

    // 32768 warps total, 8 warps (256 threads) per block -> 4096 blocks
    fold_pair_kernel<<<4096, 256>>>(p, out);
}